// round 2
// baseline (speedup 1.0000x reference)
#include <cuda_runtime.h>
#include <cstdint>
#include <cstddef>

#define BB 64      // batch
#define TT 512     // time
#define HH 256     // hidden
#define GG 1024    // 4*H
#define NCTA 128

// ---------------- device scratch (static, no allocations) ----------------
__device__ float g_xg[(size_t)TT * GG * BB];   // [T][4H][B] gate pre-activations (transposed)
__device__ float g_y0[(size_t)BB * TT * HH];   // layer-0 output, [B][T][H]
__device__ float g_hbuf[2][HH * BB];           // ping-pong h carry, TRANSPOSED [hid][b]
__device__ float g_masks[6 * BB * HH];         // (layer,{out,h,c}) masks [B][H]
__device__ unsigned g_bar_arrive;              // zero-initialized
__device__ unsigned g_bar_gen;

// ---------------- Threefry-2x32 (JAX, partitionable semantics) — VALIDATED in round 1 ----------------
__device__ __forceinline__ uint32_t rotl32(uint32_t x, int n) { return __funnelshift_l(x, x, n); }

__device__ __forceinline__ void tf2x32(uint32_t k0, uint32_t k1, uint32_t x0, uint32_t x1,
                                       uint32_t& o0, uint32_t& o1) {
    uint32_t ks2 = k0 ^ k1 ^ 0x1BD11BDAu;
    x0 += k0; x1 += k1;
#define TFR(r) { x0 += x1; x1 = rotl32(x1, (r)); x1 ^= x0; }
    TFR(13) TFR(15) TFR(26) TFR(6)   x0 += k1;  x1 += ks2 + 1u;
    TFR(17) TFR(29) TFR(16) TFR(24)  x0 += ks2; x1 += k0 + 2u;
    TFR(13) TFR(15) TFR(26) TFR(6)   x0 += k0;  x1 += k1 + 3u;
    TFR(17) TFR(29) TFR(16) TFR(24)  x0 += k1;  x1 += ks2 + 4u;
    TFR(13) TFR(15) TFR(26) TFR(6)   x0 += ks2; x1 += k0 + 5u;
#undef TFR
    o0 = x0; o1 = x1;
}

__global__ void compute_masks_kernel() {
    int idx = blockIdx.x * 256 + threadIdx.x;
    if (idx >= 6 * BB * HH) return;
    int l = idx / (3 * BB * HH);
    int j = (idx / (BB * HH)) % 3;
    uint32_t e = (uint32_t)(idx % (BB * HH));
    uint32_t a0, a1, b0, b1, c0, c1;
    tf2x32(0u, 42u, 0u, (uint32_t)l, a0, a1);
    tf2x32(a0, a1, 0u, (uint32_t)j, b0, b1);
    tf2x32(b0, b1, 0u, e, c0, c1);
    uint32_t bits = c0 ^ c1;
    float u = __uint_as_float((bits >> 9) | 0x3f800000u) - 1.0f;
    g_masks[idx] = (u < 0.75f) ? (1.0f / 0.75f) : 0.0f;
}

__global__ void zero_state_kernel() {
    int i = blockIdx.x * 256 + threadIdx.x;
    if (i < HH * BB) {
        g_hbuf[0][i] = 0.0f;
        g_hbuf[1][i] = 0.0f;
    }
}

// ---------------- big GEMM: xg[t][g][b] = sum_k A[b][t][k]*W[g][k] + bih[g]+bhh[g] ----------------
__global__ void gemm_xg_kernel(const float* __restrict__ Aext, const float* __restrict__ W,
                               const float* __restrict__ bih, const float* __restrict__ bhh,
                               int use_y0) {
    const float* A = use_y0 ? g_y0 : Aext;
    __shared__ float As[16][68];
    __shared__ float Bs[16][68];
    int tid = threadIdx.x;
    int lr = tid >> 2;            // 0..63
    int lc = (tid & 3) << 2;      // k offset 0,4,8,12
    int m = blockIdx.x * 64 + lr; // m = t*64 + b
    const float* Arow = A + ((size_t)(m & 63) * TT + (size_t)(m >> 6)) * HH;
    const float* Wrow = W + (size_t)(blockIdx.y * 64 + lr) * 256;
    int tx = tid & 15, ty = tid >> 4;
    float acc[4][4] = {};
    for (int k0 = 0; k0 < 256; k0 += 16) {
        float4 av = *reinterpret_cast<const float4*>(Arow + k0 + lc);
        float4 wv = *reinterpret_cast<const float4*>(Wrow + k0 + lc);
        As[lc + 0][lr] = av.x; As[lc + 1][lr] = av.y; As[lc + 2][lr] = av.z; As[lc + 3][lr] = av.w;
        Bs[lc + 0][lr] = wv.x; Bs[lc + 1][lr] = wv.y; Bs[lc + 2][lr] = wv.z; Bs[lc + 3][lr] = wv.w;
        __syncthreads();
#pragma unroll
        for (int kk = 0; kk < 16; kk++) {
            float4 a4 = *reinterpret_cast<const float4*>(&As[kk][ty << 2]);
            float4 w4 = *reinterpret_cast<const float4*>(&Bs[kk][tx << 2]);
            float a[4] = {a4.x, a4.y, a4.z, a4.w};
            float w[4] = {w4.x, w4.y, w4.z, w4.w};
#pragma unroll
            for (int i = 0; i < 4; i++)
#pragma unroll
                for (int jj = 0; jj < 4; jj++) acc[i][jj] += a[i] * w[jj];
        }
        __syncthreads();
    }
    int n0 = blockIdx.y * 64 + (tx << 2);
    float bv[4];
#pragma unroll
    for (int jj = 0; jj < 4; jj++) bv[jj] = bih[n0 + jj] + bhh[n0 + jj];
#pragma unroll
    for (int i = 0; i < 4; i++) {
        int m2 = blockIdx.x * 64 + (ty << 2) + i;
        size_t tt = (size_t)(m2 >> 6), bb = (size_t)(m2 & 63);
        size_t base = (tt * GG + (size_t)n0) * BB + bb;
#pragma unroll
        for (int jj = 0; jj < 4; jj++)
            g_xg[base + (size_t)jj * BB] = acc[i][jj] + bv[jj];
    }
}

// ---------------- grid barrier (generation counter, sense-free) ----------------
__device__ __forceinline__ void grid_sync_leader() {
    unsigned gen = *((volatile unsigned*)&g_bar_gen);
    unsigned old = atomicAdd(&g_bar_arrive, 1u);
    if (old == NCTA - 1u) {
        atomicExch(&g_bar_arrive, 0u);
        __threadfence();
        atomicAdd(&g_bar_gen, 1u);
    } else {
        while (*((volatile unsigned*)&g_bar_gen) == gen) { }
    }
    __threadfence();
}

// ---------------- persistent per-layer recurrence kernel ----------------
// 128 CTAs x 128 threads, all co-resident (128 <= 148 SMs, 1 CTA/SM at this smem).
// CTA owns 2 hidden units; warp = (hid_local, b-half); lanes = 32 batches.
__global__ void __launch_bounds__(128, 1) lstm_layer_kernel(const float* __restrict__ Whh,
                                                            float* __restrict__ yext, int layer) {
    extern __shared__ float sm[];
    float* hsT = sm;           // [256 k][64 b]
    float* W4  = sm + 16384;   // [2 hid][256 k][4 gates]
    const int tid = threadIdx.x;
    const int wid = tid >> 5, lane = tid & 31;
    const int hid_local = wid >> 1;
    const int b = ((wid & 1) << 5) | lane;
    const int hid = (blockIdx.x << 1) + hid_local;

    // stage W_hh (gate-interleaved) once for the whole sequence
    for (int i = tid; i < 2048; i += 128) {
        int hl = i >> 10, rem = i & 1023, k = rem >> 2, gate = rem & 3;
        W4[i] = Whh[((size_t)(gate << 8) + (size_t)((blockIdx.x << 1) + hl)) * 256 + k];
    }

    const int mi = (b << 8) + hid;
    const float mo  = g_masks[(layer * 3 + 0) * BB * HH + mi];
    const float mh  = g_masks[(layer * 3 + 1) * BB * HH + mi];
    const float mcm = g_masks[(layer * 3 + 2) * BB * HH + mi];
    float c = 0.0f;   // cell state lives in a register for all 512 steps

    const float4* w4p = reinterpret_cast<const float4*>(W4 + (hid_local << 10));
    float* y = layer ? yext : g_y0;
    float* yrow = y + (size_t)b * (TT * HH) + hid;
    __syncthreads();

    for (int t = 0; t < TT; t++) {
        const int cur = t & 1;
        // prefetch xg(t) — coalesced over b, streams from DRAM
        size_t xbase = ((size_t)t * GG + (size_t)hid) * BB + b;
        float xi = __ldg(&g_xg[xbase]);
        float xf = __ldg(&g_xg[xbase + (size_t)256 * BB]);
        float xc = __ldg(&g_xg[xbase + (size_t)512 * BB]);
        float xo = __ldg(&g_xg[xbase + (size_t)768 * BB]);

        // stage h(t) [hid][b] -> smem; .cg mandatory (L1 incoherent across SMs mid-kernel)
        {
            const float4* src = reinterpret_cast<const float4*>(g_hbuf[cur]);
            float4* dst = reinterpret_cast<float4*>(hsT);
#pragma unroll
            for (int i = 0; i < 32; i++)
                dst[tid + (i << 7)] = __ldcg(src + tid + (i << 7));
        }
        __syncthreads();

        // gate dot-products: W via broadcast LDS.128, h via conflict-free LDS.32
        float ai = 0.f, af = 0.f, ac = 0.f, ao = 0.f;
        const float* hcol = hsT + b;
#pragma unroll 16
        for (int k = 0; k < 256; k++) {
            float h = hcol[k << 6];
            float4 w = w4p[k];
            ai += h * w.x; af += h * w.y; ac += h * w.z; ao += h * w.w;
        }

        float gi = ai + xi, gf = af + xf, gc = ac + xc, go = ao + xo;
        float i_ = 1.0f / (1.0f + expf(-gi));
        float f_ = 1.0f / (1.0f + expf(-gf));
        float o_ = 1.0f / (1.0f + expf(-go));
        float cn = f_ * c + i_ * tanhf(gc);
        float hn = o_ * tanhf(cn);
        c = cn * mcm;

        yrow[(size_t)t * HH] = hn * mo;
        __stcg(&g_hbuf[cur ^ 1][(hid << 6) + b], hn * mh);

        __threadfence();
        __syncthreads();          // all CTA threads' writes precede leader arrival
        if (tid == 0) grid_sync_leader();
        __syncthreads();
    }
}

// ---------------- launch (7 graph nodes total) ----------------
extern "C" void kernel_launch(void* const* d_in, const int* in_sizes, int n_in,
                              void* d_out, int out_size) {
    const float* x    = (const float*)d_in[0];
    const float* Wih0 = (const float*)d_in[1];
    const float* Whh0 = (const float*)d_in[2];
    const float* bih0 = (const float*)d_in[3];
    const float* bhh0 = (const float*)d_in[4];
    const float* Wih1 = (const float*)d_in[5];
    const float* Whh1 = (const float*)d_in[6];
    const float* bih1 = (const float*)d_in[7];
    const float* bhh1 = (const float*)d_in[8];
    float* out = (float*)d_out;

    const int smem = (16384 + 2048) * 4;  // 73728 B
    cudaFuncSetAttribute(lstm_layer_kernel, cudaFuncAttributeMaxDynamicSharedMemorySize, smem);

    compute_masks_kernel<<<(6 * BB * HH + 255) / 256, 256>>>();

    // layer 0
    zero_state_kernel<<<(HH * BB + 255) / 256, 256>>>();
    gemm_xg_kernel<<<dim3((TT * BB) / 64, GG / 64), 256>>>(x, Wih0, bih0, bhh0, 0);
    lstm_layer_kernel<<<NCTA, 128, smem>>>(Whh0, nullptr, 0);

    // layer 1
    zero_state_kernel<<<(HH * BB + 255) / 256, 256>>>();
    gemm_xg_kernel<<<dim3((TT * BB) / 64, GG / 64), 256>>>(nullptr, Wih1, bih1, bhh1, 1);
    lstm_layer_kernel<<<NCTA, 128, smem>>>(Whh1, out, 1);
}